// round 2
// baseline (speedup 1.0000x reference)
#include <cuda_runtime.h>
#include <math.h>

#define B 512
#define M 1024
#define KEY 128
#define VAL 128
#define RIMH 256
#define NH 4          // READ_H and COMB_H
#define KH 32         // KEY/NH
#define INV_SQRT32 0.17677669529663687f

// scratch (allocation-free rule: __device__ globals)
__device__ float g_mq[B * KEY];        // [512,128]
__device__ float g_ans[B * 2 * VAL];   // [512,2,128]

// ---------------------------------------------------------------------------
// Kernel 1: s = state @ Wst^T + bst ; mq = [s, latent] @ Wq^T + bq
// ---------------------------------------------------------------------------
__global__ __launch_bounds__(128) void mq_kernel(
    const float* __restrict__ state,    // [B,128]
    const float* __restrict__ latent,   // [B,64]
    const float* __restrict__ Wst,      // [64,128]
    const float* __restrict__ bst,      // [64]
    const float* __restrict__ Wq,       // [128,128]
    const float* __restrict__ bq)       // [128]
{
    int b = blockIdx.x;
    int t = threadIdx.x;  // 0..127
    __shared__ float st[128];
    __shared__ float lat[64];
    __shared__ float sv[64];
    st[t] = state[b * 128 + t];
    if (t < 64) lat[t] = latent[b * 64 + t];
    __syncthreads();
    if (t < 64) {
        float a = bst[t];
        const float* wr = Wst + t * 128;
#pragma unroll 8
        for (int i = 0; i < 128; i++) a += st[i] * wr[i];
        sv[t] = a;
    }
    __syncthreads();
    {
        float a = bq[t];
        const float* wr = Wq + t * 128;
#pragma unroll 8
        for (int i = 0; i < 64; i++) a += sv[i] * wr[i];
#pragma unroll 8
        for (int i = 0; i < 64; i++) a += lat[i] * wr[64 + i];
        g_mq[b * 128 + t] = a;
    }
}

// ---------------------------------------------------------------------------
// Kernel 2: streaming multi-head memory read with online softmax.
// grid = (B, 2 banks), 256 threads (8 warps). One warp per row (strided),
// software-pipelined (prefetch next row's key+val before consuming current).
// Each lane loads float4 of the 128-wide key/val row; lanes 8h..8h+7 own
// head h (cols 32h..32h+31). Segment shfl-reduce gives per-head score.
// ---------------------------------------------------------------------------
__global__ __launch_bounds__(256) void memread_kernel(
    const float* __restrict__ ekeys, const float* __restrict__ evals,
    const float* __restrict__ hkeys, const float* __restrict__ hvals)
{
    int b = blockIdx.x;
    int bank = blockIdx.y;
    const float* keys = (bank == 0 ? ekeys : hkeys) + (size_t)b * M * KEY;
    const float* vals = (bank == 0 ? evals : hvals) + (size_t)b * M * VAL;

    __shared__ __align__(16) float qs[128];
    __shared__ float s_max[8][NH];
    __shared__ float s_den[8][NH];
    __shared__ __align__(16) float s_acc[8][128];

    int t = threadIdx.x;
    if (t < 128) qs[t] = g_mq[b * 128 + t];
    __syncthreads();

    int w = t >> 5, lane = t & 31;
    float4 qv = reinterpret_cast<const float4*>(qs)[lane];

    const float4* kp = reinterpret_cast<const float4*>(keys) + lane;
    const float4* vp = reinterpret_cast<const float4*>(vals) + lane;

    float mmax = -INFINITY, den = 0.f;
    float4 acc = make_float4(0.f, 0.f, 0.f, 0.f);

    // prefetch first row
    float4 kr = __ldg(&kp[w * 32]);
    float4 vr = __ldg(&vp[w * 32]);

#pragma unroll 4
    for (int m = w; m < M; m += 8) {
        float4 kc = kr, vc = vr;
        int mn = m + 8;
        if (mn < M) {                       // prefetch next row
            kr = __ldg(&kp[mn * 32]);
            vr = __ldg(&vp[mn * 32]);
        }
        float p = kc.x * qv.x + kc.y * qv.y + kc.z * qv.z + kc.w * qv.w;
        // reduce within 8-lane head segment
        p += __shfl_xor_sync(0xffffffffu, p, 1, 8);
        p += __shfl_xor_sync(0xffffffffu, p, 2, 8);
        p += __shfl_xor_sync(0xffffffffu, p, 4, 8);
        float score = p * INV_SQRT32;
        float nm = fmaxf(mmax, score);
        float corr = __expf(mmax - nm);
        float pe = __expf(score - nm);
        den = den * corr + pe;
        acc.x = acc.x * corr + pe * vc.x;
        acc.y = acc.y * corr + pe * vc.y;
        acc.z = acc.z * corr + pe * vc.z;
        acc.w = acc.w * corr + pe * vc.w;
        mmax = nm;
    }

    if ((lane & 7) == 0) {
        s_max[w][lane >> 3] = mmax;
        s_den[w][lane >> 3] = den;
    }
    reinterpret_cast<float4*>(s_acc[w])[lane] = acc;
    __syncthreads();

    if (t < 128) {
        int h = t >> 5;
        float gm = -INFINITY;
#pragma unroll
        for (int ww = 0; ww < 8; ww++) gm = fmaxf(gm, s_max[ww][h]);
        float d = 0.f, num = 0.f;
#pragma unroll
        for (int ww = 0; ww < 8; ww++) {
            float c = __expf(s_max[ww][h] - gm);
            d += s_den[ww][h] * c;
            num += s_acc[ww][t] * c;
        }
        g_ans[((size_t)b * 2 + bank) * 128 + t] = num / d;
    }
}

// ---------------------------------------------------------------------------
// Kernel 3: combiner. 4 batches per block (512 threads = 4 x 128), so each
// weight matrix is read once per 4 batches (L1/L2 resident).
// ---------------------------------------------------------------------------
__global__ __launch_bounds__(512) void combine_kernel(
    const float* __restrict__ rim,      // [B,256]
    const float* __restrict__ Whq, const float* __restrict__ bhq,   // [128,256],[128]
    const float* __restrict__ Wmk, const float* __restrict__ bmk,   // [128,128],[128]
    const float* __restrict__ Wmv, const float* __restrict__ bmv,   // [128,128],[128]
    const float* __restrict__ Wq, const float* __restrict__ Wk,
    const float* __restrict__ Wv, const float* __restrict__ Wo,
    float* __restrict__ out)            // [B,128]
{
    int s = threadIdx.x >> 7;          // sub-batch 0..3
    int o = threadIdx.x & 127;         // output index 0..127
    int b = blockIdx.x * 4 + s;

    __shared__ float sh_rim[4][256];
    __shared__ float sh_a0[4][128], sh_a1[4][128];
    __shared__ float sh_qv[4][128];
    __shared__ float sh_k0[4][128], sh_k1[4][128], sh_v0[4][128], sh_v1[4][128];
    __shared__ float sh_qp[4][128], sh_kp0[4][128], sh_kp1[4][128],
                     sh_vp0[4][128], sh_vp1[4][128];
    __shared__ float sh_ctx[4][128];

    sh_rim[s][o]       = rim[b * 256 + o];
    sh_rim[s][o + 128] = rim[b * 256 + 128 + o];
    sh_a0[s][o] = g_ans[((size_t)b * 2 + 0) * 128 + o];
    sh_a1[s][o] = g_ans[((size_t)b * 2 + 1) * 128 + o];
    __syncthreads();

    // phase 2: first linears
    {
        float a = bhq[o];
        const float* wr = Whq + o * 256;
#pragma unroll 8
        for (int i = 0; i < 256; i++) a += sh_rim[s][i] * wr[i];
        sh_qv[s][o] = a;

        float k0 = bmk[o], k1 = bmk[o];
        const float* wmk = Wmk + o * 128;
#pragma unroll 8
        for (int i = 0; i < 128; i++) {
            k0 += sh_a0[s][i] * wmk[i];
            k1 += sh_a1[s][i] * wmk[i];
        }
        sh_k0[s][o] = k0; sh_k1[s][o] = k1;

        float v0 = bmv[o], v1 = bmv[o];
        const float* wmv = Wmv + o * 128;
#pragma unroll 8
        for (int i = 0; i < 128; i++) {
            v0 += sh_a0[s][i] * wmv[i];
            v1 += sh_a1[s][i] * wmv[i];
        }
        sh_v0[s][o] = v0; sh_v1[s][o] = v1;
    }
    __syncthreads();

    // phase 3: MHA in-projections (no bias)
    {
        float a = 0.f;
        const float* wr = Wq + o * 128;
#pragma unroll 8
        for (int i = 0; i < 128; i++) a += sh_qv[s][i] * wr[i];
        sh_qp[s][o] = a;

        float k0 = 0.f, k1 = 0.f;
        const float* wk = Wk + o * 128;
#pragma unroll 8
        for (int i = 0; i < 128; i++) {
            k0 += sh_k0[s][i] * wk[i];
            k1 += sh_k1[s][i] * wk[i];
        }
        sh_kp0[s][o] = k0; sh_kp1[s][o] = k1;

        float v0 = 0.f, v1 = 0.f;
        const float* wv = Wv + o * 128;
#pragma unroll 8
        for (int i = 0; i < 128; i++) {
            v0 += sh_v0[s][i] * wv[i];
            v1 += sh_v1[s][i] * wv[i];
        }
        sh_vp0[s][o] = v0; sh_vp1[s][o] = v1;
    }
    __syncthreads();

    // phase 4: 2-way softmax attention per head (hd = 32)
    {
        int h = o >> 5;
        int base = h * 32;
        float a0 = 0.f, a1 = 0.f;
#pragma unroll
        for (int d = 0; d < 32; d++) {
            float qd = sh_qp[s][base + d];
            a0 += qd * sh_kp0[s][base + d];
            a1 += qd * sh_kp1[s][base + d];
        }
        a0 *= INV_SQRT32; a1 *= INV_SQRT32;
        float mx = fmaxf(a0, a1);
        float e0 = __expf(a0 - mx), e1 = __expf(a1 - mx);
        float inv = 1.f / (e0 + e1);
        sh_ctx[s][o] = (e0 * sh_vp0[s][o] + e1 * sh_vp1[s][o]) * inv;
    }
    __syncthreads();

    // phase 5: out projection (no bias)
    {
        float a = 0.f;
        const float* wr = Wo + o * 128;
#pragma unroll 8
        for (int i = 0; i < 128; i++) a += sh_ctx[s][i] * wr[i];
        out[b * 128 + o] = a;
    }
}

// ---------------------------------------------------------------------------
// launch
// inputs (metadata order = setup_inputs dict order):
//  0 state [B,128]        1 task_inference_latent [B,64]   2 rim_hidden_state [B,256]
//  3 epi_keys [B,M,128]   4 epi_vals [B,M,128]
//  5 hebb_keys            6 hebb_vals
//  7 W_state [64,128]     8 b_state [64]
//  9 W_query [128,128]   10 b_query [128]
// 11 W_hq [128,256]      12 b_hq [128]
// 13 W_mk [128,128]      14 b_mk [128]
// 15 W_mv [128,128]      16 b_mv [128]
// 17 Wq [128,128] 18 Wk [128,128] 19 Wv [128,128] 20 Wo [128,128]
// ---------------------------------------------------------------------------
extern "C" void kernel_launch(void* const* d_in, const int* in_sizes, int n_in,
                              void* d_out, int out_size)
{
    const float* state  = (const float*)d_in[0];
    const float* latent = (const float*)d_in[1];
    const float* rim    = (const float*)d_in[2];
    const float* ekeys  = (const float*)d_in[3];
    const float* evals  = (const float*)d_in[4];
    const float* hkeys  = (const float*)d_in[5];
    const float* hvals  = (const float*)d_in[6];
    const float* Wst    = (const float*)d_in[7];
    const float* bst    = (const float*)d_in[8];
    const float* Wqy    = (const float*)d_in[9];
    const float* bqy    = (const float*)d_in[10];
    const float* Whq    = (const float*)d_in[11];
    const float* bhq    = (const float*)d_in[12];
    const float* Wmk    = (const float*)d_in[13];
    const float* bmk    = (const float*)d_in[14];
    const float* Wmv    = (const float*)d_in[15];
    const float* bmv    = (const float*)d_in[16];
    const float* Wq     = (const float*)d_in[17];
    const float* Wk     = (const float*)d_in[18];
    const float* Wv     = (const float*)d_in[19];
    const float* Wo     = (const float*)d_in[20];
    float* out = (float*)d_out;

    mq_kernel<<<B, 128>>>(state, latent, Wst, bst, Wqy, bqy);

    dim3 grid2(B, 2);
    memread_kernel<<<grid2, 256>>>(ekeys, evals, hkeys, hvals);

    combine_kernel<<<B / 4, 512>>>(rim, Whq, bhq, Wmk, bmk, Wmv, bmv,
                                   Wq, Wk, Wv, Wo, out);
}

// round 8
// speedup vs baseline: 1.4358x; 1.4358x over previous
#include <cuda_runtime.h>
#include <math.h>

#define B 512
#define M 1024
#define KEY 128
#define VAL 128
#define NH 4
#define INV_SQRT32 0.17677669529663687f

// scratch (allocation-free rule: __device__ globals)
__device__ float g_mq[B * KEY];        // [512,128]
__device__ float g_ans[B * 2 * VAL];   // [512,2,128]

__device__ __forceinline__ float dot4(float4 a, float4 b) {
    return a.x * b.x + a.y * b.y + a.z * b.z + a.w * b.w;
}
__device__ __forceinline__ float wreduce(float p) {
    p += __shfl_xor_sync(0xffffffffu, p, 16);
    p += __shfl_xor_sync(0xffffffffu, p, 8);
    p += __shfl_xor_sync(0xffffffffu, p, 4);
    p += __shfl_xor_sync(0xffffffffu, p, 2);
    p += __shfl_xor_sync(0xffffffffu, p, 1);
    return p;
}

// ---------------------------------------------------------------------------
// Kernel 1: s = state @ Wst^T + bst ; mq = [s, latent] @ Wq^T + bq
// Warp-per-row: coalesced float4 weight loads + shfl reduce.
// ---------------------------------------------------------------------------
__global__ __launch_bounds__(256) void mq_kernel(
    const float* __restrict__ state,    // [B,128]
    const float* __restrict__ latent,   // [B,64]
    const float* __restrict__ Wst,      // [64,128]
    const float* __restrict__ bst,      // [64]
    const float* __restrict__ Wq,       // [128,128]  (in = [s(64), lat(64)])
    const float* __restrict__ bq)       // [128]
{
    int b = blockIdx.x;
    int t = threadIdx.x;
    int wid = t >> 5, lane = t & 31;

    __shared__ __align__(16) float st[128];
    __shared__ __align__(16) float xs[128];  // [s(64), lat(64)]

    if (t < 128) st[t] = state[b * 128 + t];
    else if (t < 192) xs[64 + (t - 128)] = latent[b * 64 + (t - 128)];
    __syncthreads();

    const float4* st4 = reinterpret_cast<const float4*>(st);
    float4 sx = st4[lane];

#pragma unroll
    for (int r = wid; r < 64; r += 8) {
        float4 w = reinterpret_cast<const float4*>(Wst + r * 128)[lane];
        float p = wreduce(dot4(w, sx));
        if (lane == 0) xs[r] = p + bst[r];
    }
    __syncthreads();

    const float4* xs4 = reinterpret_cast<const float4*>(xs);
    float4 xv = xs4[lane];

#pragma unroll
    for (int r = wid; r < 128; r += 8) {
        float4 w = reinterpret_cast<const float4*>(Wq + r * 128)[lane];
        float p = wreduce(dot4(w, xv));
        if (lane == 0) g_mq[b * 128 + r] = p + bq[r];
    }
}

// ---------------------------------------------------------------------------
// Kernel 2: streaming multi-head memory read with online softmax.
// EXACT loop body that passed at R2 (471.8us run) — no prefetch variant.
// grid = (B, 2 banks), 256 threads (8 warps). One warp per row (strided).
// Lanes 8h..8h+7 own head h (cols 32h..32h+31).
// ---------------------------------------------------------------------------
__global__ __launch_bounds__(256) void memread_kernel(
    const float* __restrict__ ekeys, const float* __restrict__ evals,
    const float* __restrict__ hkeys, const float* __restrict__ hvals)
{
    int b = blockIdx.x;
    int bank = blockIdx.y;
    const float* keys = (bank == 0 ? ekeys : hkeys) + (size_t)b * M * KEY;
    const float* vals = (bank == 0 ? evals : hvals) + (size_t)b * M * VAL;

    __shared__ __align__(16) float qs[128];
    __shared__ float s_max[8][NH];
    __shared__ float s_den[8][NH];
    __shared__ __align__(16) float s_acc[8][128];

    int t = threadIdx.x;
    if (t < 128) qs[t] = g_mq[b * 128 + t];
    __syncthreads();

    int w = t >> 5, lane = t & 31;
    float4 qv = reinterpret_cast<const float4*>(qs)[lane];

    const float4* kp = reinterpret_cast<const float4*>(keys);
    const float4* vp = reinterpret_cast<const float4*>(vals);

    float mmax = -INFINITY, den = 0.f;
    float4 acc = make_float4(0.f, 0.f, 0.f, 0.f);

#pragma unroll 4
    for (int m = w; m < M; m += 8) {
        float4 kr = __ldg(&kp[m * 32 + lane]);
        float4 vr = __ldg(&vp[m * 32 + lane]);
        float p = kr.x * qv.x + kr.y * qv.y + kr.z * qv.z + kr.w * qv.w;
        p += __shfl_xor_sync(0xffffffffu, p, 1, 8);
        p += __shfl_xor_sync(0xffffffffu, p, 2, 8);
        p += __shfl_xor_sync(0xffffffffu, p, 4, 8);
        float score = p * INV_SQRT32;
        float nm = fmaxf(mmax, score);
        float corr = __expf(mmax - nm);
        float pe = __expf(score - nm);
        den = den * corr + pe;
        acc.x = acc.x * corr + pe * vr.x;
        acc.y = acc.y * corr + pe * vr.y;
        acc.z = acc.z * corr + pe * vr.z;
        acc.w = acc.w * corr + pe * vr.w;
        mmax = nm;
    }

    if ((lane & 7) == 0) {
        s_max[w][lane >> 3] = mmax;
        s_den[w][lane >> 3] = den;
    }
    reinterpret_cast<float4*>(s_acc[w])[lane] = acc;
    __syncthreads();

    if (t < 128) {
        int h = t >> 5;
        float gm = -INFINITY;
#pragma unroll
        for (int ww = 0; ww < 8; ww++) gm = fmaxf(gm, s_max[ww][h]);
        float d = 0.f, num = 0.f;
#pragma unroll
        for (int ww = 0; ww < 8; ww++) {
            float c = __expf(s_max[ww][h] - gm);
            d += s_den[ww][h] * c;
            num += s_acc[ww][t] * c;
        }
        g_ans[((size_t)b * 2 + bank) * 128 + t] = num / d;
    }
}

// ---------------------------------------------------------------------------
// Kernel 3: combiner. 4 batches per block, 512 threads = 16 warps.
// Warp-per-weight-row, coalesced loads, 4 batches share each row load.
// ---------------------------------------------------------------------------
__global__ __launch_bounds__(512) void combine_kernel(
    const float* __restrict__ rim,      // [B,256]
    const float* __restrict__ Whq, const float* __restrict__ bhq,
    const float* __restrict__ Wmk, const float* __restrict__ bmk,
    const float* __restrict__ Wmv, const float* __restrict__ bmv,
    const float* __restrict__ Wq, const float* __restrict__ Wk,
    const float* __restrict__ Wv, const float* __restrict__ Wo,
    float* __restrict__ out)            // [B,128]
{
    int t = threadIdx.x;
    int wid = t >> 5, lane = t & 31;
    int s = t >> 7, o = t & 127;
    int b0 = blockIdx.x * 4;

    __shared__ __align__(16) float sh_rim[4][256];
    __shared__ __align__(16) float sh_a[2][4][128];
    __shared__ __align__(16) float sh_qv[4][128];
    __shared__ __align__(16) float sh_k[2][4][128], sh_v[2][4][128];
    __shared__ __align__(16) float sh_qp[4][128];
    __shared__ __align__(16) float sh_kp[2][4][128], sh_vp[2][4][128];
    __shared__ __align__(16) float sh_ctx[4][128];

    sh_rim[s][o]       = rim[(b0 + s) * 256 + o];
    sh_rim[s][o + 128] = rim[(b0 + s) * 256 + 128 + o];
    sh_a[0][s][o] = g_ans[((size_t)(b0 + s) * 2 + 0) * 128 + o];
    sh_a[1][s][o] = g_ans[((size_t)(b0 + s) * 2 + 1) * 128 + o];
    __syncthreads();

    // ---- phase B: qv = rim@Whq^T+bhq ; k_m = a_m@Wmk^T+bmk ; v_m = a_m@Wmv^T+bmv
    for (int T = wid; T < 384; T += 16) {
        if (T < 128) {
            int r = T;
            float4 w1 = reinterpret_cast<const float4*>(Whq + r * 256)[lane];
            float4 w2 = reinterpret_cast<const float4*>(Whq + r * 256)[lane + 32];
            float bb = bhq[r];
#pragma unroll
            for (int ss = 0; ss < 4; ss++) {
                const float4* x4 = reinterpret_cast<const float4*>(sh_rim[ss]);
                float p = dot4(w1, x4[lane]) + dot4(w2, x4[lane + 32]);
                p = wreduce(p);
                if (lane == 0) sh_qv[ss][r] = p + bb;
            }
        } else if (T < 256) {
            int r = T - 128;
            float4 w = reinterpret_cast<const float4*>(Wmk + r * 128)[lane];
            float bb = bmk[r];
#pragma unroll
            for (int ss = 0; ss < 4; ss++) {
#pragma unroll
                for (int m = 0; m < 2; m++) {
                    float p = dot4(w, reinterpret_cast<const float4*>(sh_a[m][ss])[lane]);
                    p = wreduce(p);
                    if (lane == 0) sh_k[m][ss][r] = p + bb;
                }
            }
        } else {
            int r = T - 256;
            float4 w = reinterpret_cast<const float4*>(Wmv + r * 128)[lane];
            float bb = bmv[r];
#pragma unroll
            for (int ss = 0; ss < 4; ss++) {
#pragma unroll
                for (int m = 0; m < 2; m++) {
                    float p = dot4(w, reinterpret_cast<const float4*>(sh_a[m][ss])[lane]);
                    p = wreduce(p);
                    if (lane == 0) sh_v[m][ss][r] = p + bb;
                }
            }
        }
    }
    __syncthreads();

    // ---- phase C: qp = qv@Wq^T ; kp_m = k_m@Wk^T ; vp_m = v_m@Wv^T (no bias)
    for (int T = wid; T < 384; T += 16) {
        if (T < 128) {
            int r = T;
            float4 w = reinterpret_cast<const float4*>(Wq + r * 128)[lane];
#pragma unroll
            for (int ss = 0; ss < 4; ss++) {
                float p = wreduce(dot4(w, reinterpret_cast<const float4*>(sh_qv[ss])[lane]));
                if (lane == 0) sh_qp[ss][r] = p;
            }
        } else if (T < 256) {
            int r = T - 128;
            float4 w = reinterpret_cast<const float4*>(Wk + r * 128)[lane];
#pragma unroll
            for (int ss = 0; ss < 4; ss++) {
#pragma unroll
                for (int m = 0; m < 2; m++) {
                    float p = wreduce(dot4(w, reinterpret_cast<const float4*>(sh_k[m][ss])[lane]));
                    if (lane == 0) sh_kp[m][ss][r] = p;
                }
            }
        } else {
            int r = T - 256;
            float4 w = reinterpret_cast<const float4*>(Wv + r * 128)[lane];
#pragma unroll
            for (int ss = 0; ss < 4; ss++) {
#pragma unroll
                for (int m = 0; m < 2; m++) {
                    float p = wreduce(dot4(w, reinterpret_cast<const float4*>(sh_v[m][ss])[lane]));
                    if (lane == 0) sh_vp[m][ss][r] = p;
                }
            }
        }
    }
    __syncthreads();

    // ---- phase D: per-head 2-way softmax attention (hd = 32)
    {
        int h = o >> 5;
        int base = h * 32;
        float a0 = 0.f, a1 = 0.f;
#pragma unroll
        for (int d = 0; d < 32; d++) {
            float qd = sh_qp[s][base + d];
            a0 += qd * sh_kp[0][s][base + d];
            a1 += qd * sh_kp[1][s][base + d];
        }
        a0 *= INV_SQRT32; a1 *= INV_SQRT32;
        float mx = fmaxf(a0, a1);
        float e0 = __expf(a0 - mx), e1 = __expf(a1 - mx);
        float inv = 1.f / (e0 + e1);
        sh_ctx[s][o] = (e0 * sh_vp[0][s][o] + e1 * sh_vp[1][s][o]) * inv;
    }
    __syncthreads();

    // ---- phase E: out = ctx @ Wo^T (no bias)
    for (int T = wid; T < 128; T += 16) {
        float4 w = reinterpret_cast<const float4*>(Wo + T * 128)[lane];
#pragma unroll
        for (int ss = 0; ss < 4; ss++) {
            float p = wreduce(dot4(w, reinterpret_cast<const float4*>(sh_ctx[ss])[lane]));
            if (lane == 0) out[(b0 + ss) * 128 + T] = p;
        }
    }
}

// ---------------------------------------------------------------------------
// launch (inputs in metadata order)
// ---------------------------------------------------------------------------
extern "C" void kernel_launch(void* const* d_in, const int* in_sizes, int n_in,
                              void* d_out, int out_size)
{
    const float* state  = (const float*)d_in[0];
    const float* latent = (const float*)d_in[1];
    const float* rim    = (const float*)d_in[2];
    const float* ekeys  = (const float*)d_in[3];
    const float* evals  = (const float*)d_in[4];
    const float* hkeys  = (const float*)d_in[5];
    const float* hvals  = (const float*)d_in[6];
    const float* Wst    = (const float*)d_in[7];
    const float* bst    = (const float*)d_in[8];
    const float* Wqy    = (const float*)d_in[9];
    const float* bqy    = (const float*)d_in[10];
    const float* Whq    = (const float*)d_in[11];
    const float* bhq    = (const float*)d_in[12];
    const float* Wmk    = (const float*)d_in[13];
    const float* bmk    = (const float*)d_in[14];
    const float* Wmv    = (const float*)d_in[15];
    const float* bmv    = (const float*)d_in[16];
    const float* Wq     = (const float*)d_in[17];
    const float* Wk     = (const float*)d_in[18];
    const float* Wv     = (const float*)d_in[19];
    const float* Wo     = (const float*)d_in[20];
    float* out = (float*)d_out;

    mq_kernel<<<B, 256>>>(state, latent, Wst, bst, Wqy, bqy);

    dim3 grid2(B, 2);
    memread_kernel<<<grid2, 256>>>(ekeys, evals, hkeys, hvals);

    combine_kernel<<<B / 4, 512>>>(rim, Whq, bhq, Wmk, bmk, Wmv, bmv,
                                   Wq, Wk, Wv, Wo, out);
}